// round 2
// baseline (speedup 1.0000x reference)
#include <cuda_runtime.h>

// ---------------------------------------------------------------------------
// Problem: 3-layer GRU + linear head.
// B=64, T=512, F=128, H=512, 3H=1536, O=128. M = B*T = 32768.
// ---------------------------------------------------------------------------
#define B_SZ   64
#define T_SZ   512
#define F_SZ   128
#define H_SZ   512
#define G3_SZ  1536
#define O_SZ   128
#define M_SZ   (B_SZ * T_SZ)

#define SCAN_NBLK 128

typedef unsigned long long u64;

__device__ __forceinline__ u64 splat2(float x) {
    u64 r; asm("mov.b64 %0, {%1, %1};" : "=l"(r) : "f"(x)); return r;
}
__device__ __forceinline__ void fma2(u64 &d, u64 a, u64 b) {
    asm("fma.rn.f32x2 %0, %1, %2, %0;" : "+l"(d) : "l"(a), "l"(b));
}
__device__ __forceinline__ float2 unpack2(u64 v) {
    float2 f; asm("mov.b64 {%0, %1}, %2;" : "=f"(f.x), "=f"(f.y) : "l"(v)); return f;
}

// ---------------------------------------------------------------------------
// Scratch (device globals -- allocation-free per harness rules)
// ---------------------------------------------------------------------------
__device__ float    g_xp[(size_t)M_SZ * G3_SZ];   // input projections  [M, 1536]
__device__ float    g_hseq[(size_t)M_SZ * H_SZ];  // hidden sequence    [M, 512]
__device__ unsigned g_cnt;                        // grid barrier: monotonic ticket
__device__ unsigned g_gen;                        // grid barrier: monotonic generation

// ---------------------------------------------------------------------------
// GEMM: C[M,N] = A[M,K] @ W[N,K]^T + bias[N]
// Block tile 128x128, BK=16, 256 threads, 8x8 micro-tile, f32x2 packed FMA.
// All dims divisible by tile sizes for this problem (no edge guards needed).
// ---------------------------------------------------------------------------
__global__ void __launch_bounds__(256)
gemm_bias_kernel(const float* __restrict__ A, const float* __restrict__ W,
                 const float* __restrict__ bias, float* __restrict__ C,
                 int M, int N, int K)
{
    __shared__ float As[16][132];   // k-major, padded
    __shared__ float Ws[16][132];

    const int tid = threadIdx.x;
    const int tx  = tid & 15;       // n micro-tile index
    const int ty  = tid >> 4;       // m micro-tile index
    const int m0  = blockIdx.y * 128;
    const int n0  = blockIdx.x * 128;

    u64 acc[8][4];
#pragma unroll
    for (int i = 0; i < 8; i++)
#pragma unroll
        for (int j = 0; j < 4; j++) acc[i][j] = 0ull;

    const int lr = tid >> 2;        // row within tile (0..63), two rows per thread
    const int lk = (tid & 3) * 4;   // k offset 0/4/8/12

    for (int k0 = 0; k0 < K; k0 += 16) {
#pragma unroll
        for (int h = 0; h < 2; h++) {
            const int row = lr + h * 64;
            float4 av = *(const float4*)(A + (size_t)(m0 + row) * K + k0 + lk);
            float4 wv = *(const float4*)(W + (size_t)(n0 + row) * K + k0 + lk);
            As[lk + 0][row] = av.x; As[lk + 1][row] = av.y;
            As[lk + 2][row] = av.z; As[lk + 3][row] = av.w;
            Ws[lk + 0][row] = wv.x; Ws[lk + 1][row] = wv.y;
            Ws[lk + 2][row] = wv.z; Ws[lk + 3][row] = wv.w;
        }
        __syncthreads();
#pragma unroll
        for (int k = 0; k < 16; k++) {
            float4 a0 = *(const float4*)&As[k][ty * 8];
            float4 a1 = *(const float4*)&As[k][ty * 8 + 4];
            ulonglong2 w01 = *(const ulonglong2*)&Ws[k][tx * 8];      // n pairs (0,1),(2,3)
            ulonglong2 w23 = *(const ulonglong2*)&Ws[k][tx * 8 + 4];  // n pairs (4,5),(6,7)
            float av[8] = {a0.x, a0.y, a0.z, a0.w, a1.x, a1.y, a1.z, a1.w};
#pragma unroll
            for (int i = 0; i < 8; i++) {
                u64 as = splat2(av[i]);
                fma2(acc[i][0], as, w01.x);
                fma2(acc[i][1], as, w01.y);
                fma2(acc[i][2], as, w23.x);
                fma2(acc[i][3], as, w23.y);
            }
        }
        __syncthreads();
    }

    // epilogue
#pragma unroll
    for (int i = 0; i < 8; i++) {
        const int m = m0 + ty * 8 + i;
        float* crow = C + (size_t)m * N + n0 + tx * 8;
#pragma unroll
        for (int j = 0; j < 4; j++) {
            float2 v = unpack2(acc[i][j]);
            const int n = n0 + tx * 8 + j * 2;
            crow[j * 2 + 0] = v.x + bias[n + 0];
            crow[j * 2 + 1] = v.y + bias[n + 1];
        }
    }
}

// ---------------------------------------------------------------------------
// Persistent GRU scan kernel.
// 128 blocks (one per SM): block = (batch tile of 16) x (hidden tile of 16).
// Whh rows for this block's 16 hidden units (3 gates x 16 rows x 512) stay
// resident in SMEM across all 512 time steps.
// Threads: jg = tid&7 (hidden pair), bg = (tid>>3)&7 (batch pair), ks = tid>>6
// (k-split of 4). Thread computes 2b x 2j x 3gate partial dots over 128 k's
// using packed f32x2 FMA (j-pair packed), then 4-way k reduction in SMEM.
// ---------------------------------------------------------------------------
struct ScanSmem {
    float ws[3][8][1028];   // [gate][jpair][k*2 + p], p = j within pair. pitch 1028 floats
    float hs[16][516];      // h_{t-1} tile, pitch 516
    float red[256][13];     // k-split reduction buffer (12 partials + pad)
    float xs[16][52];       // xp staging: [b][gate*16 + j]
    float bhs[48];          // bhh slice: [gate*16 + j]
};

__global__ void __launch_bounds__(256)
scan_kernel(const float* __restrict__ Whh, const float* __restrict__ bhh,
            const float* __restrict__ xp, float* __restrict__ hseq)
{
    extern __shared__ ScanSmem smem[];
    ScanSmem& s = smem[0];

    const int tid = threadIdx.x;
    const int jg  = tid & 7;
    const int bg  = (tid >> 3) & 7;
    const int ks  = tid >> 6;
    const int bt  = blockIdx.x >> 5;   // 0..3
    const int jt  = blockIdx.x & 31;   // 0..31
    const int b0  = bt * 16;
    const int j0  = jt * 16;

    // Snapshot barrier counters (monotonic across launches/replays).
    unsigned cnt0 = 0, gen0 = 0;
    if (tid == 0) {
        cnt0 = atomicAdd(&g_cnt, 0u);
        gen0 = atomicAdd(&g_gen, 0u);
    }

    // ---- load resident weights (48 rows x 512) into interleaved-pair layout
    for (int i = tid; i < 48 * 128; i += 256) {
        const int rl = i >> 7;          // 0..47
        const int k4 = i & 127;         // 0..127
        const int gg = rl >> 4;
        const int jj = rl & 15;
        float4 v = *(const float4*)(Whh + (size_t)(gg * H_SZ + j0 + jj) * H_SZ + k4 * 4);
        const int jp = jj >> 1, p = jj & 1;
        float* w = &s.ws[gg][jp][0];
        w[(k4 * 4 + 0) * 2 + p] = v.x;
        w[(k4 * 4 + 1) * 2 + p] = v.y;
        w[(k4 * 4 + 2) * 2 + p] = v.z;
        w[(k4 * 4 + 3) * 2 + p] = v.w;
    }
    if (tid < 48) s.bhs[tid] = bhh[(tid >> 4) * H_SZ + j0 + (tid & 15)];
    __syncthreads();

    for (int t = 0; t < T_SZ; t++) {
        // ---- stage h_{t-1} tile (16 x 512) and xp slice (16 x 48)
        if (t == 0) {
            float4 z = make_float4(0.f, 0.f, 0.f, 0.f);
            for (int i = tid; i < 16 * 129; i += 256)
                ((float4*)&s.hs[0][0])[i] = z;
        } else {
            for (int i = tid; i < 16 * 128; i += 256) {
                const int b = i >> 7, k4 = i & 127;
                float4 v = *(const float4*)(hseq + ((size_t)(b0 + b) * T_SZ + (t - 1)) * H_SZ + k4 * 4);
                *(float4*)&s.hs[b][k4 * 4] = v;
            }
        }
        if (tid < 192) {
            const int b = tid / 12, r = tid % 12, gg = r >> 2, q = r & 3;
            float4 v = *(const float4*)(xp + ((size_t)(b0 + b) * T_SZ + t) * G3_SZ + gg * H_SZ + j0 + q * 4);
            *(float4*)&s.xs[b][gg * 16 + q * 4] = v;
        }
        __syncthreads();

        // ---- partial dots over this thread's 128 k's
        u64 acc[2][3];
#pragma unroll
        for (int b = 0; b < 2; b++)
#pragma unroll
            for (int g = 0; g < 3; g++) acc[b][g] = 0ull;

        {
            const float* h0p = &s.hs[bg * 2 + 0][ks * 128];
            const float* h1p = &s.hs[bg * 2 + 1][ks * 128];
            const float* wr  = &s.ws[0][jg][ks * 256];
            const float* wz  = &s.ws[1][jg][ks * 256];
            const float* wn  = &s.ws[2][jg][ks * 256];
#pragma unroll 4
            for (int c = 0; c < 32; c++) {
                float4 h0 = *(const float4*)(h0p + c * 4);
                float4 h1 = *(const float4*)(h1p + c * 4);
                ulonglong2 rA = *(const ulonglong2*)(wr + c * 8);
                ulonglong2 rB = *(const ulonglong2*)(wr + c * 8 + 4);
                ulonglong2 zA = *(const ulonglong2*)(wz + c * 8);
                ulonglong2 zB = *(const ulonglong2*)(wz + c * 8 + 4);
                ulonglong2 nA = *(const ulonglong2*)(wn + c * 8);
                ulonglong2 nB = *(const ulonglong2*)(wn + c * 8 + 4);
                u64 a0 = splat2(h0.x), a1 = splat2(h0.y), a2 = splat2(h0.z), a3 = splat2(h0.w);
                u64 c0 = splat2(h1.x), c1 = splat2(h1.y), c2 = splat2(h1.z), c3 = splat2(h1.w);
                fma2(acc[0][0], a0, rA.x); fma2(acc[0][0], a1, rA.y);
                fma2(acc[0][0], a2, rB.x); fma2(acc[0][0], a3, rB.y);
                fma2(acc[0][1], a0, zA.x); fma2(acc[0][1], a1, zA.y);
                fma2(acc[0][1], a2, zB.x); fma2(acc[0][1], a3, zB.y);
                fma2(acc[0][2], a0, nA.x); fma2(acc[0][2], a1, nA.y);
                fma2(acc[0][2], a2, nB.x); fma2(acc[0][2], a3, nB.y);
                fma2(acc[1][0], c0, rA.x); fma2(acc[1][0], c1, rA.y);
                fma2(acc[1][0], c2, rB.x); fma2(acc[1][0], c3, rB.y);
                fma2(acc[1][1], c0, zA.x); fma2(acc[1][1], c1, zA.y);
                fma2(acc[1][1], c2, zB.x); fma2(acc[1][1], c3, zB.y);
                fma2(acc[1][2], c0, nA.x); fma2(acc[1][2], c1, nA.y);
                fma2(acc[1][2], c2, nB.x); fma2(acc[1][2], c3, nB.y);
            }
        }

        // ---- k-split reduction + gates + state update
#pragma unroll
        for (int b = 0; b < 2; b++)
#pragma unroll
            for (int g = 0; g < 3; g++) {
                float2 v = unpack2(acc[b][g]);
                s.red[tid][b * 6 + g * 2 + 0] = v.x;
                s.red[tid][b * 6 + g * 2 + 1] = v.y;
            }
        __syncthreads();

        if (ks == 0) {   // tid < 64 finalizes
            float tot[12];
#pragma unroll
            for (int i = 0; i < 12; i++)
                tot[i] = s.red[tid][i] + s.red[tid + 64][i] +
                         s.red[tid + 128][i] + s.red[tid + 192][i];
#pragma unroll
            for (int b = 0; b < 2; b++) {
                const int bl = bg * 2 + b;
#pragma unroll
                for (int p = 0; p < 2; p++) {
                    const int jl = jg * 2 + p;
                    float dr = tot[b * 6 + 0 + p];
                    float dz = tot[b * 6 + 2 + p];
                    float dn = tot[b * 6 + 4 + p];
                    float xr = s.xs[bl][jl];
                    float xz = s.xs[bl][16 + jl];
                    float xn = s.xs[bl][32 + jl];
                    float rg = 1.f / (1.f + expf(-(xr + dr + s.bhs[jl])));
                    float zg = 1.f / (1.f + expf(-(xz + dz + s.bhs[16 + jl])));
                    float ng = tanhf(xn + rg * (dn + s.bhs[32 + jl]));
                    float hp = s.hs[bl][j0 + jl];       // h_{t-1}[b][j] (zeros at t=0)
                    float hv = (1.f - zg) * ng + zg * hp;
                    hseq[((size_t)(b0 + bl) * T_SZ + t) * H_SZ + j0 + jl] = hv;
                }
            }
        }

        // ---- grid barrier (sense-free monotonic counters)
        __syncthreads();
        if (tid == 0) {
            __threadfence();
            unsigned ticket = atomicAdd(&g_cnt, 1u) - cnt0;     // 0-based this launch
            const unsigned bar = (unsigned)t + 1u;
            if (ticket == bar * SCAN_NBLK - 1u) {
                atomicAdd(&g_gen, 1u);
            } else {
                const unsigned tgt = gen0 + bar;
                while ((int)(atomicAdd(&g_gen, 0u) - tgt) < 0) { }
            }
            __threadfence();
        }
        __syncthreads();
    }
}

// ---------------------------------------------------------------------------
// Launch
// ---------------------------------------------------------------------------
extern "C" void kernel_launch(void* const* d_in, const int* in_sizes, int n_in,
                              void* d_out, int out_size)
{
    (void)in_sizes; (void)n_in; (void)out_size;
    const float* x    = (const float*)d_in[0];
    const float* Wih0 = (const float*)d_in[1];
    const float* Whh0 = (const float*)d_in[2];
    const float* bih0 = (const float*)d_in[3];
    const float* bhh0 = (const float*)d_in[4];
    const float* Wih1 = (const float*)d_in[5];
    const float* Whh1 = (const float*)d_in[6];
    const float* bih1 = (const float*)d_in[7];
    const float* bhh1 = (const float*)d_in[8];
    const float* Wih2 = (const float*)d_in[9];
    const float* Whh2 = (const float*)d_in[10];
    const float* bih2 = (const float*)d_in[11];
    const float* bhh2 = (const float*)d_in[12];
    const float* Wout = (const float*)d_in[13];
    const float* bout = (const float*)d_in[14];
    float* out = (float*)d_out;

    cudaFuncSetAttribute(scan_kernel, cudaFuncAttributeMaxDynamicSharedMemorySize,
                         (int)sizeof(ScanSmem));

    void *xp_v = nullptr, *hs_v = nullptr;
    cudaGetSymbolAddress(&xp_v, g_xp);
    cudaGetSymbolAddress(&hs_v, g_hseq);
    float* xp = (float*)xp_v;
    float* hs = (float*)hs_v;

    const dim3 blk(256);
    const dim3 g_proj(G3_SZ / 128, M_SZ / 128);   // 12 x 256
    const dim3 g_head(O_SZ / 128,  M_SZ / 128);   // 1 x 256
    const size_t scan_smem = sizeof(ScanSmem);

    // Layer 0
    gemm_bias_kernel<<<g_proj, blk>>>(x,  Wih0, bih0, xp, M_SZ, G3_SZ, F_SZ);
    scan_kernel<<<SCAN_NBLK, blk, scan_smem>>>(Whh0, bhh0, xp, hs);
    // Layer 1
    gemm_bias_kernel<<<g_proj, blk>>>(hs, Wih1, bih1, xp, M_SZ, G3_SZ, H_SZ);
    scan_kernel<<<SCAN_NBLK, blk, scan_smem>>>(Whh1, bhh1, xp, hs);
    // Layer 2
    gemm_bias_kernel<<<g_proj, blk>>>(hs, Wih2, bih2, xp, M_SZ, G3_SZ, H_SZ);
    scan_kernel<<<SCAN_NBLK, blk, scan_smem>>>(Whh2, bhh2, xp, hs);
    // Head
    gemm_bias_kernel<<<g_head, blk>>>(hs, Wout, bout, out, M_SZ, O_SZ, H_SZ);
}

// round 3
// speedup vs baseline: 1.1438x; 1.1438x over previous
#include <cuda_runtime.h>

// ---------------------------------------------------------------------------
// 3-layer GRU + linear head. B=64, T=512, F=128, H=512, 3H=1536, O=128.
// ---------------------------------------------------------------------------
#define B_SZ   64
#define T_SZ   512
#define F_SZ   128
#define H_SZ   512
#define G3_SZ  1536
#define O_SZ   128
#define M_SZ   (B_SZ * T_SZ)

#define SCAN_NBLK  128
#define GRP_BLKS   32          // blocks per batch group (share one barrier)
#define CNT_PER_LAUNCH (T_SZ * GRP_BLKS)   // 16384

typedef unsigned long long u64;

__device__ __forceinline__ u64 splat2(float x) {
    u64 r; asm("mov.b64 %0, {%1, %1};" : "=l"(r) : "f"(x)); return r;
}
__device__ __forceinline__ void fma2(u64 &d, u64 a, u64 b) {
    asm("fma.rn.f32x2 %0, %1, %2, %0;" : "+l"(d) : "l"(a), "l"(b));
}
__device__ __forceinline__ float2 unpack2(u64 v) {
    float2 f; asm("mov.b64 {%0, %1}, %2;" : "=f"(f.x), "=f"(f.y) : "l"(v)); return f;
}
__device__ __forceinline__ unsigned ld_acq(const unsigned* p) {
    unsigned v; asm volatile("ld.global.acquire.gpu.u32 %0, [%1];" : "=r"(v) : "l"(p)); return v;
}

// ---------------------------------------------------------------------------
// Scratch (device globals -- allocation-free per harness rules)
// ---------------------------------------------------------------------------
__device__ float    g_xp[(size_t)M_SZ * G3_SZ];
__device__ float    g_hseq[(size_t)M_SZ * H_SZ];
__device__ unsigned g_cnt4[4 * 32];   // per-group arrive counters, 128B apart
__device__ unsigned g_gen4[4 * 32];   // per-group generation flags, 128B apart

// ---------------------------------------------------------------------------
// GEMM: C[M,N] = A[M,K] @ W[N,K]^T + bias[N].  128x128x16 tile, f32x2 FMA.
// ---------------------------------------------------------------------------
__global__ void __launch_bounds__(256)
gemm_bias_kernel(const float* __restrict__ A, const float* __restrict__ W,
                 const float* __restrict__ bias, float* __restrict__ C,
                 int M, int N, int K)
{
    __shared__ float As[16][132];
    __shared__ float Ws[16][132];

    const int tid = threadIdx.x;
    const int tx  = tid & 15;
    const int ty  = tid >> 4;
    const int m0  = blockIdx.y * 128;
    const int n0  = blockIdx.x * 128;

    u64 acc[8][4];
#pragma unroll
    for (int i = 0; i < 8; i++)
#pragma unroll
        for (int j = 0; j < 4; j++) acc[i][j] = 0ull;

    const int lr = tid >> 2;
    const int lk = (tid & 3) * 4;

    for (int k0 = 0; k0 < K; k0 += 16) {
#pragma unroll
        for (int h = 0; h < 2; h++) {
            const int row = lr + h * 64;
            float4 av = *(const float4*)(A + (size_t)(m0 + row) * K + k0 + lk);
            float4 wv = *(const float4*)(W + (size_t)(n0 + row) * K + k0 + lk);
            As[lk + 0][row] = av.x; As[lk + 1][row] = av.y;
            As[lk + 2][row] = av.z; As[lk + 3][row] = av.w;
            Ws[lk + 0][row] = wv.x; Ws[lk + 1][row] = wv.y;
            Ws[lk + 2][row] = wv.z; Ws[lk + 3][row] = wv.w;
        }
        __syncthreads();
#pragma unroll
        for (int k = 0; k < 16; k++) {
            float4 a0 = *(const float4*)&As[k][ty * 8];
            float4 a1 = *(const float4*)&As[k][ty * 8 + 4];
            ulonglong2 w01 = *(const ulonglong2*)&Ws[k][tx * 8];
            ulonglong2 w23 = *(const ulonglong2*)&Ws[k][tx * 8 + 4];
            float av[8] = {a0.x, a0.y, a0.z, a0.w, a1.x, a1.y, a1.z, a1.w};
#pragma unroll
            for (int i = 0; i < 8; i++) {
                u64 as = splat2(av[i]);
                fma2(acc[i][0], as, w01.x);
                fma2(acc[i][1], as, w01.y);
                fma2(acc[i][2], as, w23.x);
                fma2(acc[i][3], as, w23.y);
            }
        }
        __syncthreads();
    }

#pragma unroll
    for (int i = 0; i < 8; i++) {
        const int m = m0 + ty * 8 + i;
        float* crow = C + (size_t)m * N + n0 + tx * 8;
#pragma unroll
        for (int j = 0; j < 4; j++) {
            float2 v = unpack2(acc[i][j]);
            const int n = n0 + tx * 8 + j * 2;
            crow[j * 2 + 0] = v.x + bias[n + 0];
            crow[j * 2 + 1] = v.y + bias[n + 1];
        }
    }
}

// ---------------------------------------------------------------------------
// Persistent GRU scan. 128 blocks = 4 batch-groups x 32 j-tiles.
// 512 threads: jg = tid&7 (j pair), bg = (tid>>3)&7 (batch pair), ks = tid>>6
// (k-split of 8, 64 k's per thread). Whh tile (96KB) SMEM-resident for all T.
// Barrier is group-local (32 blocks), ld.acquire spin (no atomic RMW storm).
// ---------------------------------------------------------------------------
struct ScanSmem {
    float ws[3][8][1028];   // [gate][jpair][k*2+p] interleaved pairs
    float hs[16][516];      // h_{t-1} tile
    float red[512][12];     // k-split partials (pitch 12 floats: conflict-free f4)
    float bhs[48];
};

__global__ void __launch_bounds__(512)
scan_kernel(const float* __restrict__ Whh, const float* __restrict__ bhh,
            const float* __restrict__ xp, float* __restrict__ hseq)
{
    extern __shared__ ScanSmem smem[];
    ScanSmem& s = smem[0];

    const int tid = threadIdx.x;
    const int jg  = tid & 7;
    const int bg  = (tid >> 3) & 7;
    const int ks  = tid >> 6;
    const int bt  = blockIdx.x >> 5;   // batch group 0..3
    const int jt  = blockIdx.x & 31;   // j tile 0..31
    const int b0  = bt * 16;
    const int j0  = jt * 16;

    unsigned* cnt = &g_cnt4[bt * 32];
    unsigned* gen = &g_gen4[bt * 32];

    // Launch-robust baselines: counters advance by exactly CNT_PER_LAUNCH /
    // T_SZ per launch; before the step-0 barrier completes, cnt can exceed the
    // launch base by at most GRP_BLKS-1 < CNT_PER_LAUNCH, so rounding is safe.
    unsigned base_cnt = 0, base_gen = 0;
    if (tid == 0) {
        base_cnt = ld_acq(cnt) & ~(unsigned)(CNT_PER_LAUNCH - 1);
        base_gen = ld_acq(gen);
        base_gen -= base_gen % T_SZ;
    }

    // Resident weights: 48 rows x 512, pair-interleaved over j.
    for (int i = tid; i < 48 * 128; i += 512) {
        const int rl = i >> 7, k4 = i & 127;
        const int gg = rl >> 4, jj = rl & 15;
        float4 v = *(const float4*)(Whh + (size_t)(gg * H_SZ + j0 + jj) * H_SZ + k4 * 4);
        const int jp = jj >> 1, p = jj & 1;
        float* w = &s.ws[gg][jp][0];
        w[(k4 * 4 + 0) * 2 + p] = v.x;
        w[(k4 * 4 + 1) * 2 + p] = v.y;
        w[(k4 * 4 + 2) * 2 + p] = v.z;
        w[(k4 * 4 + 3) * 2 + p] = v.w;
    }
    if (tid < 48) s.bhs[tid] = bhh[(tid >> 4) * H_SZ + j0 + (tid & 15)];
    __syncthreads();

    for (int t = 0; t < T_SZ; t++) {
        // ---- finalizer xp prefetch (t's xp is ready in gmem; hide LDG latency)
        float2 xv[2][3];
        if (ks == 0) {
#pragma unroll
            for (int b = 0; b < 2; b++) {
                const size_t row = ((size_t)(b0 + bg * 2 + b) * T_SZ + t) * G3_SZ;
#pragma unroll
                for (int g = 0; g < 3; g++)
                    xv[b][g] = *(const float2*)(xp + row + g * H_SZ + j0 + jg * 2);
            }
        }

        // ---- stage h_{t-1} (16 x 512)
        if (t == 0) {
            float4 z = make_float4(0.f, 0.f, 0.f, 0.f);
            for (int i = tid; i < 16 * 129; i += 512)
                ((float4*)&s.hs[0][0])[i] = z;
        } else {
#pragma unroll
            for (int u = 0; u < 4; u++) {
                const int i = tid + u * 512;
                const int b = i >> 7, k4 = i & 127;
                float4 v = *(const float4*)(hseq + ((size_t)(b0 + b) * T_SZ + (t - 1)) * H_SZ + k4 * 4);
                *(float4*)&s.hs[b][k4 * 4] = v;
            }
        }
        __syncthreads();

        // ---- partial dots over this thread's 64 k's
        u64 acc[2][3];
#pragma unroll
        for (int b = 0; b < 2; b++)
#pragma unroll
            for (int g = 0; g < 3; g++) acc[b][g] = 0ull;

        {
            const float* h0p = &s.hs[bg * 2 + 0][ks * 64];
            const float* h1p = &s.hs[bg * 2 + 1][ks * 64];
            const float* wr  = &s.ws[0][jg][ks * 128];
            const float* wz  = &s.ws[1][jg][ks * 128];
            const float* wn  = &s.ws[2][jg][ks * 128];
#pragma unroll 4
            for (int c = 0; c < 16; c++) {
                float4 h0 = *(const float4*)(h0p + c * 4);
                float4 h1 = *(const float4*)(h1p + c * 4);
                ulonglong2 rA = *(const ulonglong2*)(wr + c * 8);
                ulonglong2 rB = *(const ulonglong2*)(wr + c * 8 + 4);
                ulonglong2 zA = *(const ulonglong2*)(wz + c * 8);
                ulonglong2 zB = *(const ulonglong2*)(wz + c * 8 + 4);
                ulonglong2 nA = *(const ulonglong2*)(wn + c * 8);
                ulonglong2 nB = *(const ulonglong2*)(wn + c * 8 + 4);
                u64 a0 = splat2(h0.x), a1 = splat2(h0.y), a2 = splat2(h0.z), a3 = splat2(h0.w);
                u64 c0 = splat2(h1.x), c1 = splat2(h1.y), c2 = splat2(h1.z), c3 = splat2(h1.w);
                fma2(acc[0][0], a0, rA.x); fma2(acc[0][0], a1, rA.y);
                fma2(acc[0][0], a2, rB.x); fma2(acc[0][0], a3, rB.y);
                fma2(acc[0][1], a0, zA.x); fma2(acc[0][1], a1, zA.y);
                fma2(acc[0][1], a2, zB.x); fma2(acc[0][1], a3, zB.y);
                fma2(acc[0][2], a0, nA.x); fma2(acc[0][2], a1, nA.y);
                fma2(acc[0][2], a2, nB.x); fma2(acc[0][2], a3, nB.y);
                fma2(acc[1][0], c0, rA.x); fma2(acc[1][0], c1, rA.y);
                fma2(acc[1][0], c2, rB.x); fma2(acc[1][0], c3, rB.y);
                fma2(acc[1][1], c0, zA.x); fma2(acc[1][1], c1, zA.y);
                fma2(acc[1][1], c2, zB.x); fma2(acc[1][1], c3, zB.y);
                fma2(acc[1][2], c0, nA.x); fma2(acc[1][2], c1, nA.y);
                fma2(acc[1][2], c2, nB.x); fma2(acc[1][2], c3, nB.y);
            }
        }

        // ---- write partials (3 x float4 per thread; pitch 12 -> conflict-free)
        {
            float v[12];
#pragma unroll
            for (int b = 0; b < 2; b++)
#pragma unroll
                for (int g = 0; g < 3; g++) {
                    float2 p = unpack2(acc[b][g]);
                    v[b * 6 + g * 2 + 0] = p.x;
                    v[b * 6 + g * 2 + 1] = p.y;
                }
            float* rp = &s.red[tid][0];
            *(float4*)(rp + 0) = make_float4(v[0], v[1], v[2], v[3]);
            *(float4*)(rp + 4) = make_float4(v[4], v[5], v[6], v[7]);
            *(float4*)(rp + 8) = make_float4(v[8], v[9], v[10], v[11]);
        }
        __syncthreads();

        // ---- finalize: tid < 64 sums 8 k-slices, applies gates, stores h_t
        if (ks == 0) {
            float4 t0 = make_float4(0.f, 0.f, 0.f, 0.f), t1 = t0, t2 = t0;
#pragma unroll
            for (int sidx = 0; sidx < 8; sidx++) {
                const float* rp = &s.red[tid + sidx * 64][0];
                float4 a = *(const float4*)(rp + 0);
                float4 b = *(const float4*)(rp + 4);
                float4 c = *(const float4*)(rp + 8);
                t0.x += a.x; t0.y += a.y; t0.z += a.z; t0.w += a.w;
                t1.x += b.x; t1.y += b.y; t1.z += b.z; t1.w += b.w;
                t2.x += c.x; t2.y += c.y; t2.z += c.z; t2.w += c.w;
            }
            float tot[12] = {t0.x, t0.y, t0.z, t0.w, t1.x, t1.y, t1.z, t1.w,
                             t2.x, t2.y, t2.z, t2.w};
            const int jl0 = jg * 2;
#pragma unroll
            for (int b = 0; b < 2; b++) {
                const int bl = bg * 2 + b;
                float2 hv;
#pragma unroll
                for (int p = 0; p < 2; p++) {
                    const int jl = jl0 + p;
                    float dr = tot[b * 6 + 0 + p];
                    float dz = tot[b * 6 + 2 + p];
                    float dn = tot[b * 6 + 4 + p];
                    float xr = (p == 0) ? xv[b][0].x : xv[b][0].y;
                    float xz = (p == 0) ? xv[b][1].x : xv[b][1].y;
                    float xn = (p == 0) ? xv[b][2].x : xv[b][2].y;
                    float rg = 1.f / (1.f + __expf(-(xr + dr + s.bhs[jl])));
                    float zg = 1.f / (1.f + __expf(-(xz + dz + s.bhs[16 + jl])));
                    float ng = tanhf(xn + rg * (dn + s.bhs[32 + jl]));
                    float hp = s.hs[bl][j0 + jl];
                    float h  = (1.f - zg) * ng + zg * hp;
                    if (p == 0) hv.x = h; else hv.y = h;
                }
                *(float2*)(hseq + ((size_t)(b0 + bl) * T_SZ + t) * H_SZ + j0 + jl0) = hv;
            }
        }

        // ---- group-local barrier: atomic arrive, ld.acquire spin + nanosleep
        __syncthreads();
        if (tid == 0) {
            __threadfence();
            unsigned ticket = atomicAdd(cnt, 1u) - base_cnt;   // 0-based
            const unsigned bar = (unsigned)t + 1u;
            if (ticket == bar * GRP_BLKS - 1u) {
                atomicAdd(gen, 1u);
            } else {
                const unsigned tgt = base_gen + bar;
                while ((int)(ld_acq(gen) - tgt) < 0) __nanosleep(40);
            }
        }
        __syncthreads();
    }
}

// ---------------------------------------------------------------------------
// Launch
// ---------------------------------------------------------------------------
extern "C" void kernel_launch(void* const* d_in, const int* in_sizes, int n_in,
                              void* d_out, int out_size)
{
    (void)in_sizes; (void)n_in; (void)out_size;
    const float* x    = (const float*)d_in[0];
    const float* Wih0 = (const float*)d_in[1];
    const float* Whh0 = (const float*)d_in[2];
    const float* bih0 = (const float*)d_in[3];
    const float* bhh0 = (const float*)d_in[4];
    const float* Wih1 = (const float*)d_in[5];
    const float* Whh1 = (const float*)d_in[6];
    const float* bih1 = (const float*)d_in[7];
    const float* bhh1 = (const float*)d_in[8];
    const float* Wih2 = (const float*)d_in[9];
    const float* Whh2 = (const float*)d_in[10];
    const float* bih2 = (const float*)d_in[11];
    const float* bhh2 = (const float*)d_in[12];
    const float* Wout = (const float*)d_in[13];
    const float* bout = (const float*)d_in[14];
    float* out = (float*)d_out;

    cudaFuncSetAttribute(scan_kernel, cudaFuncAttributeMaxDynamicSharedMemorySize,
                         (int)sizeof(ScanSmem));

    void *xp_v = nullptr, *hs_v = nullptr;
    cudaGetSymbolAddress(&xp_v, g_xp);
    cudaGetSymbolAddress(&hs_v, g_hseq);
    float* xpd = (float*)xp_v;
    float* hs  = (float*)hs_v;

    const dim3 gblk(256), sblk(512);
    const dim3 g_proj(G3_SZ / 128, M_SZ / 128);
    const dim3 g_head(O_SZ / 128,  M_SZ / 128);
    const size_t scan_smem = sizeof(ScanSmem);

    gemm_bias_kernel<<<g_proj, gblk>>>(x,  Wih0, bih0, xpd, M_SZ, G3_SZ, F_SZ);
    scan_kernel<<<SCAN_NBLK, sblk, scan_smem>>>(Whh0, bhh0, xpd, hs);
    gemm_bias_kernel<<<g_proj, gblk>>>(hs, Wih1, bih1, xpd, M_SZ, G3_SZ, H_SZ);
    scan_kernel<<<SCAN_NBLK, sblk, scan_smem>>>(Whh1, bhh1, xpd, hs);
    gemm_bias_kernel<<<g_proj, gblk>>>(hs, Wih2, bih2, xpd, M_SZ, G3_SZ, H_SZ);
    scan_kernel<<<SCAN_NBLK, sblk, scan_smem>>>(Whh2, bhh2, xpd, hs);
    gemm_bias_kernel<<<g_head, gblk>>>(hs, Wout, bout, out, M_SZ, O_SZ, H_SZ);
}